// round 2
// baseline (speedup 1.0000x reference)
#include <cuda_runtime.h>
#include <mma.h>

using namespace nvcuda;

#define CC 2048
#define HWN 4096

// ---------------- device scratch ----------------
__device__ float g_sum[128];
__device__ float g_sumsq[128];
__device__ float g_hs4[4*1024*192];   // 4 K-splits of sampled raw dot products
__device__ float g_tf[1024*128];
__device__ float g_tw[1024];
__device__ float g_loss[16];

// ---------------- tiny init ----------------
__global__ void k_init0() {
    int t = threadIdx.x;
    if (t < 128) { g_sum[t] = 0.f; g_sumsq[t] = 0.f; }
}

// ---------------- cp.async helpers ----------------
__device__ __forceinline__ void cpasync16(void* s, const void* g) {
    unsigned sa = (unsigned)__cvta_generic_to_shared(s);
    asm volatile("cp.async.cg.shared.global [%0], [%1], 16;\n" :: "r"(sa), "l"(g));
}
__device__ __forceinline__ void cpcommit() { asm volatile("cp.async.commit_group;\n"); }
template<int N> __device__ __forceinline__ void cpwait() {
    asm volatile("cp.async.wait_group %0;\n" :: "n"(N));
}

// ---------------- fused: conv1 BN-stats (tf32 WMMA) + sampled exact conv ---------
#define ALD 132
#define WLD 36
#define STAGE_A (32*ALD)     // 4224 floats
#define STAGE_W (128*WLD)    // 4608 floats
#define NSTAGE 3
#define DYN_FLOATS (NSTAGE*(STAGE_A+STAGE_W))   // 26496 floats = 105984 B
#define NSAMPB 64            // sampled blocks (16 images x 4 K-splits)

__global__ __launch_bounds__(256, 2)
void k_fused(const float* __restrict__ feats, const float* __restrict__ W1,
             const float* __restrict__ Wa1,  const int* __restrict__ labels) {
    extern __shared__ float dyn[];
    const int tid = threadIdx.x;

    if (blockIdx.x < NSAMPB) {
        // ================= sampled path: exact fp32 conv at 64 pixels =================
        const int z = blockIdx.x & 3;        // K-split
        const int b = blockIdx.x >> 2;       // image
        float* Fs  = dyn;                    // [64][33]
        float* Ws2 = dyn + 64*33;            // [192][33]
        int*   pix = (int*)(dyn + 64*33 + 192*33);

        if (tid < 64) pix[tid] = 0;
        __syncthreads();
        if (tid < 32) {
            const int lane = tid;
            // detect int64 vs int32 label storage
            int probe = 0;
            #pragma unroll
            for (int i = lane; i < 64; i += 32) probe |= labels[2*(i*512)+1];
            unsigned any = __ballot_sync(0xffffffffu, probe != 0);
            const bool is64 = (any == 0u);
            const long long* L64 = (const long long*)labels;
            int base = 0;
            for (int c = 0; c < 128; c++) {
                if (base >= 64) break;
                int p = (c << 5) + lane;
                long long v = is64 ? L64[(size_t)b*HWN + p]
                                   : (long long)labels[(size_t)b*HWN + p];
                bool valid = (v == 1);
                unsigned m = __ballot_sync(0xffffffffu, valid);
                int pre = __popc(m & ((1u << lane) - 1u));
                if (valid && base + pre < 64) pix[base + pre] = p;
                base += __popc(m);
            }
        }
        __syncthreads();

        float acc[4][12];
        #pragma unroll
        for (int i = 0; i < 4; i++)
            #pragma unroll
            for (int j = 0; j < 12; j++) acc[i][j] = 0.f;

        const int pg = tid & 15;   // 4 pixels each
        const int cg = tid >> 4;   // 12 channels each
        const size_t fb = (size_t)b*CC*HWN;
        const int kbase = z * 512;

        for (int chn = 0; chn < 16; chn++) {
            int k0 = kbase + chn*32;
            __syncthreads();
            #pragma unroll
            for (int i = 0; i < 8; i++) {
                int idx = tid + i*256;
                int px = idx >> 5, kk = idx & 31;
                Fs[px*33 + kk] = feats[fb + (size_t)(k0+kk)*HWN + pix[px]];
            }
            #pragma unroll
            for (int i = 0; i < 24; i++) {
                int idx = tid + i*256;
                int r = idx >> 5, kk = idx & 31;
                Ws2[r*33 + kk] = (r < 128) ? W1[r*CC + k0 + kk]
                                           : Wa1[(r-128)*CC + k0 + kk];
            }
            __syncthreads();
            #pragma unroll 4
            for (int kk = 0; kk < 32; kk++) {
                float fv[4];
                #pragma unroll
                for (int i = 0; i < 4; i++) fv[i] = Fs[(pg*4 + i)*33 + kk];
                #pragma unroll
                for (int j = 0; j < 12; j++) {
                    float w = Ws2[(cg*12 + j)*33 + kk];
                    #pragma unroll
                    for (int i = 0; i < 4; i++) acc[i][j] += fv[i]*w;
                }
            }
        }
        #pragma unroll
        for (int i = 0; i < 4; i++)
            #pragma unroll
            for (int j = 0; j < 12; j++)
                g_hs4[(size_t)z*196608 + (b*64 + pg*4 + i)*192 + cg*12 + j] = acc[i][j];
        return;
    }

    // ================= conv1 + BN-stats path (tf32 WMMA, cp.async pipeline) =========
    const int cb = blockIdx.x - NSAMPB;
    const int b  = cb >> 5;
    const int p0 = (cb & 31) * 128;
    const float* F = feats + (size_t)b*CC*HWN + p0;

    float* As = dyn;                       // [NSTAGE][32][ALD]
    float* Ws = dyn + NSTAGE*STAGE_A;      // [NSTAGE][128][WLD]

    const int wid = tid >> 5;
    const int wr  = wid & 1;    // 64-pixel half
    const int wc  = wid >> 1;   // 32-channel quarter

    wmma::fragment<wmma::accumulator,16,16,8,float> acc[4][2];
    #pragma unroll
    for (int i = 0; i < 4; i++)
        #pragma unroll
        for (int j = 0; j < 2; j++) wmma::fill_fragment(acc[i][j], 0.f);

    auto issue = [&](int kc) {
        int s = kc % NSTAGE;
        float* A = As + s*STAGE_A;
        float* W = Ws + s*STAGE_W;
        const float* Fg = F + (size_t)(kc*32)*HWN;
        const float* Wg = W1 + kc*32;
        #pragma unroll
        for (int i = 0; i < 4; i++) {
            int c = tid + i*256;
            int k = c >> 5, px4 = (c & 31) << 2;
            cpasync16(A + k*ALD + px4, Fg + (size_t)k*HWN + px4);
        }
        #pragma unroll
        for (int i = 0; i < 4; i++) {
            int c = tid + i*256;
            int ch = c >> 3, k4 = (c & 7) << 2;
            cpasync16(W + ch*WLD + k4, Wg + ch*CC + k4);
        }
        cpcommit();
    };

    issue(0); issue(1);

    for (int kc = 0; kc < 64; kc++) {
        if (kc + 2 < 64) { issue(kc + 2); cpwait<2>(); }
        else             { cpwait<0>(); }
        __syncthreads();
        const float* Ab = As + (kc % NSTAGE)*STAGE_A;
        const float* Wb = Ws + (kc % NSTAGE)*STAGE_W;
        #pragma unroll
        for (int ks = 0; ks < 32; ks += 8) {
            wmma::fragment<wmma::matrix_a,16,16,8,wmma::precision::tf32,wmma::col_major> af[4];
            #pragma unroll
            for (int i = 0; i < 4; i++) {
                wmma::load_matrix_sync(af[i], Ab + ks*ALD + wr*64 + i*16, ALD);
                #pragma unroll
                for (int e = 0; e < af[i].num_elements; e++)
                    af[i].x[e] = wmma::__float_to_tf32(af[i].x[e]);
            }
            wmma::fragment<wmma::matrix_b,16,16,8,wmma::precision::tf32,wmma::col_major> bf[2];
            #pragma unroll
            for (int j = 0; j < 2; j++) {
                wmma::load_matrix_sync(bf[j], Wb + (wc*32 + j*16)*WLD + ks, WLD);
                #pragma unroll
                for (int e = 0; e < bf[j].num_elements; e++)
                    bf[j].x[e] = wmma::__float_to_tf32(bf[j].x[e]);
            }
            #pragma unroll
            for (int i = 0; i < 4; i++)
                #pragma unroll
                for (int j = 0; j < 2; j++)
                    wmma::mma_sync(acc[i][j], af[i], bf[j], acc[i][j]);
        }
        __syncthreads();
    }

    // Epilogue: C tile -> smem, per-channel sum/sumsq over 128 pixels
    float* Cs = dyn;  // 128 x 132 fp32 (reuse, fits in DYN_FLOATS)
    #pragma unroll
    for (int i = 0; i < 4; i++)
        #pragma unroll
        for (int j = 0; j < 2; j++)
            wmma::store_matrix_sync(Cs + (wr*64 + i*16)*ALD + wc*32 + j*16,
                                    acc[i][j], ALD, wmma::mem_row_major);
    __syncthreads();
    if (tid < 128) {
        float s = 0.f, s2 = 0.f;
        #pragma unroll 4
        for (int p = 0; p < 128; p++) {
            float v = Cs[p*ALD + tid];
            s += v; s2 += v*v;
        }
        atomicAdd(&g_sum[tid], s);
        atomicAdd(&g_sumsq[tid], s2);
    }
}

// ---------------- per-pixel: BN apply + ReLU + conv2 + normalize + attention -------------
__global__ void k_proj(const float* __restrict__ b1, const float* __restrict__ gamma,
                       const float* __restrict__ beta, const float* __restrict__ W2,
                       const float* __restrict__ b2,  const float* __restrict__ ba1,
                       const float* __restrict__ Wa2, const float* __restrict__ ba2) {
    __shared__ float xr[128];
    __shared__ float ar[64];
    __shared__ float red[128];
    const int t = threadIdx.x;
    const int pid = blockIdx.x;
    {
        float h = g_hs4[pid*192 + t] + g_hs4[196608 + pid*192 + t]
                + g_hs4[2*196608 + pid*192 + t] + g_hs4[3*196608 + pid*192 + t]
                + b1[t];
        float m   = g_sum[t] * (1.f/65536.f);
        float var = g_sumsq[t] * (1.f/65536.f) - m*m;
        float mean = m + b1[t];
        float istd = rsqrtf(var + 1e-5f);
        float xn = (h - mean) * istd * gamma[t] + beta[t];
        xr[t] = fmaxf(xn, 0.f);
    }
    if (t < 64) {
        float ha = g_hs4[pid*192 + 128 + t] + g_hs4[196608 + pid*192 + 128 + t]
                 + g_hs4[2*196608 + pid*192 + 128 + t] + g_hs4[3*196608 + pid*192 + 128 + t];
        ar[t] = fmaxf(ha + ba1[t], 0.f);
    }
    __syncthreads();

    float acc = b2[t];
    #pragma unroll 8
    for (int k = 0; k < 128; k++) acc += W2[t*128 + k] * xr[k];

    red[t] = acc*acc;
    __syncthreads();
    for (int s = 64; s > 0; s >>= 1) { if (t < s) red[t] += red[t+s]; __syncthreads(); }
    float rinv = 1.f / fmaxf(sqrtf(red[0]), 1e-12f);
    g_tf[pid*128 + t] = acc * rinv;

    if (t < 32) {
        float z = Wa2[t]*ar[t] + Wa2[t+32]*ar[t+32];
        #pragma unroll
        for (int o = 16; o > 0; o >>= 1) z += __shfl_down_sync(0xffffffffu, z, o);
        if (t == 0) g_tw[pid] = 1.f / (1.f + expf(-(z + ba2[0])));
    }
}

// ---------------- per-image contrastive loss ----------------
__global__ __launch_bounds__(256) void k_loss() {
    extern __shared__ float sm[];
    float* tfs   = sm;            // 64*128
    float* tws   = sm + 8192;     // 64
    float* simM  = sm + 8256;     // 64*65
    float* denom = sm + 12416;    // 64
    float* red   = sm + 12480;    // 256
    const int t = threadIdx.x;
    const int b = blockIdx.x;

    for (int i = t; i < 8192; i += 256) tfs[i] = g_tf[b*8192 + i];
    if (t < 64) tws[t] = g_tw[b*64 + t];
    __syncthreads();

    const int i  = t >> 2;
    const int j0 = (t & 3) << 4;
    float acc[16];
    #pragma unroll
    for (int j = 0; j < 16; j++) acc[j] = 0.f;
    const float4* fi = reinterpret_cast<const float4*>(tfs + i*128);
    #pragma unroll 4
    for (int k4 = 0; k4 < 32; k4++) {
        float4 a = fi[k4];
        #pragma unroll
        for (int j = 0; j < 16; j++) {
            float4 c = reinterpret_cast<const float4*>(tfs + (j0 + j)*128)[k4];
            acc[j] += a.x*c.x + a.y*c.y + a.z*c.z + a.w*c.w;
        }
    }
    #pragma unroll
    for (int j = 0; j < 16; j++) simM[i*65 + j0 + j] = acc[j] / 0.1f;
    __syncthreads();

    if (t < 64) {
        float d = 0.f;
        for (int j = 0; j < 64; j++) d += expf(simM[t*65 + j]);
        denom[t] = d;
    }
    __syncthreads();

    float lacc = 0.f;
    float di = denom[i];
    float twi = tws[i];
    #pragma unroll
    for (int j = 0; j < 16; j++) {
        int jj = j0 + j;
        float s = simM[i*65 + jj];
        if (s > 0.7f && jj != i) {
            float lp = logf(expf(s)/di + 1e-10f);
            lacc += twi * tws[jj] * lp;
        }
    }
    red[t] = lacc;
    __syncthreads();
    for (int sft = 128; sft > 0; sft >>= 1) { if (t < sft) red[t] += red[t+sft]; __syncthreads(); }
    if (t == 0) {
        float tsum = 0.f;
        for (int j = 0; j < 64; j++) tsum += tws[j];
        g_loss[b] = -(0.1f/0.07f) * red[0] / tsum;
    }
}

// ---------------- final mean * LOSS_WEIGHT ----------------
__global__ void k_final(float* out) {
    int t = threadIdx.x;
    float v = (t < 16) ? g_loss[t] : 0.f;
    #pragma unroll
    for (int o = 16; o > 0; o >>= 1) v += __shfl_down_sync(0xffffffffu, v, o);
    if (t == 0) out[0] = (v / 16.0f) * 0.1f;
}

// ---------------- launch ----------------
extern "C" void kernel_launch(void* const* d_in, const int* in_sizes, int n_in,
                              void* d_out, int out_size) {
    const float* feats = (const float*)d_in[0];
    const int*   labels= (const int*)d_in[1];
    const float* W1   = (const float*)d_in[2];
    const float* b1   = (const float*)d_in[3];
    const float* gamma= (const float*)d_in[4];
    const float* beta = (const float*)d_in[5];
    const float* W2   = (const float*)d_in[6];
    const float* b2   = (const float*)d_in[7];
    const float* Wa1  = (const float*)d_in[8];
    const float* ba1  = (const float*)d_in[9];
    const float* Wa2  = (const float*)d_in[10];
    const float* ba2  = (const float*)d_in[11];

    cudaFuncSetAttribute(k_fused, cudaFuncAttributeMaxDynamicSharedMemorySize,
                         DYN_FLOATS*4);
    cudaFuncSetAttribute(k_loss, cudaFuncAttributeMaxDynamicSharedMemorySize, 53248);

    k_init0<<<1, 256>>>();
    k_fused<<<NSAMPB + 512, 256, DYN_FLOATS*4>>>(feats, W1, Wa1, labels);
    k_proj<<<1024, 128>>>(b1, gamma, beta, W2, b2, ba1, Wa2, ba2);
    k_loss<<<16, 256, 50944>>>();
    k_final<<<1, 32>>>((float*)d_out);
}